// round 4
// baseline (speedup 1.0000x reference)
#include <cuda_runtime.h>

// GRU_8211977470410
// Bidirectional GRU (H=32, in=1), B=2048, T=512, MLP head -> sigmoid, out [B,1] fp32.
//
// Key insight: jax.lax.scan(reverse=True) stores ys[t] at the original index,
// so ys_b[-1] is the FIRST step of the reverse scan: GRU(h=0, x[:, T-1]).
// Only the forward recurrence needs the full 512-step scan.
//
// Mapping: 1 warp = 2 batch rows processed concurrently. lane = hidden unit.
// Per lane: 3 rows of W_hh_f (r/z/n) held as 48 packed f32x2 registers,
// hidden state replicated per lane as 16 f32x2 per batch. Matvec = 6
// independent chains of 16 fma.rn.f32x2 (FFMA2: 2x fp32 throughput on sm_103a).
// h exchange across lanes via shared memory (STS + LDS.128), not shuffles.

#define HDIM 32
#define FULLMASK 0xffffffffu

typedef unsigned long long u64;

__device__ __forceinline__ u64 pack2(float lo, float hi) {
    u64 d;
    asm("mov.b64 %0, {%1, %2};" : "=l"(d) : "f"(lo), "f"(hi));
    return d;
}
__device__ __forceinline__ void unpack2(u64 v, float& lo, float& hi) {
    asm("mov.b64 {%0, %1}, %2;" : "=f"(lo), "=f"(hi) : "l"(v));
}
__device__ __forceinline__ u64 ffma2(u64 a, u64 b, u64 c) {
    u64 d;
    asm("fma.rn.f32x2 %0, %1, %2, %3;" : "=l"(d) : "l"(a), "l"(b), "l"(c));
    return d;
}
__device__ __forceinline__ float sigm(float x) {
    // 1/(1+exp(-x)): MUFU.EX2 + MUFU.RCP path, ~2 ulp — plenty for 1e-3.
    return __fdividef(1.0f, 1.0f + __expf(-x));
}
__device__ __forceinline__ float tanh_fast(float x) {
    // tanh(x) = 1 - 2/(exp(2x)+1); exp2-based, saturates correctly at +-1.
    float e = __expf(2.0f * x);
    return 1.0f - __fdividef(2.0f, e + 1.0f);
}

__global__ void __launch_bounds__(32)
gru_bidir_kernel(const float* __restrict__ x,
                 const float* __restrict__ Wih_f, const float* __restrict__ Whh_f,
                 const float* __restrict__ bih_f, const float* __restrict__ bhh_f,
                 const float* __restrict__ Wih_b, const float* __restrict__ bih_b,
                 const float* __restrict__ bhh_b,
                 const float* __restrict__ W1, const float* __restrict__ b1v,
                 const float* __restrict__ W2, const float* __restrict__ b2v,
                 float* __restrict__ out, int B, int T)
{
    __shared__ __align__(16) float sbuf[2][80];   // per batch: [0:32) h exch, [32:64) concat, [64:80) h1

    const int lane = threadIdx.x;
    const int bA = blockIdx.x * 2;
    const int bB = bA + 1;
    const bool has2 = (bB < B);

    const int rr = lane, rz = lane + HDIM, rn = lane + 2 * HDIM;

    // ---- load forward W_hh rows (r,z,n for this lane) as packed f32x2 ----
    u64 wr[16], wz[16], wn[16];
    {
        const float4* pr = reinterpret_cast<const float4*>(Whh_f + rr * HDIM);
        const float4* pz = reinterpret_cast<const float4*>(Whh_f + rz * HDIM);
        const float4* pn = reinterpret_cast<const float4*>(Whh_f + rn * HDIM);
#pragma unroll
        for (int i = 0; i < 8; i++) {
            float4 a = pr[i]; wr[2 * i] = pack2(a.x, a.y); wr[2 * i + 1] = pack2(a.z, a.w);
            float4 c = pz[i]; wz[2 * i] = pack2(c.x, c.y); wz[2 * i + 1] = pack2(c.z, c.w);
            float4 d = pn[i]; wn[2 * i] = pack2(d.x, d.y); wn[2 * i + 1] = pack2(d.z, d.w);
        }
    }
    const float wir = Wih_f[rr], wiz = Wih_f[rz], win = Wih_f[rn];
    const float bir = bih_f[rr], biz = bih_f[rz], bin_ = bih_f[rn];
    const u64 bhr = pack2(bhh_f[rr], 0.0f);
    const u64 bhz = pack2(bhh_f[rz], 0.0f);
    const u64 bhn = pack2(bhh_f[rn], 0.0f);

    const float* xA = x + (size_t)bA * T;
    const float* xB = x + (size_t)(has2 ? bB : bA) * T;

    // replicated hidden state (16 f32x2 per batch), plus this lane's own scalar h
    u64 h0[16], h1[16];
#pragma unroll
    for (int i = 0; i < 16; i++) { h0[i] = 0ull; h1[i] = 0ull; }
    float hs0 = 0.0f, hs1 = 0.0f;

    float xa = xA[0], xb = xB[0];

    for (int t = 0; t < T; ++t) {
        // prefetch next x (hidden behind the matvec)
        float xna = 0.0f, xnb = 0.0f;
        if (t + 1 < T) { xna = xA[t + 1]; xnb = xB[t + 1]; }

        // ---- hidden matvec: 6 independent FFMA2 chains ----
        u64 ar0 = bhr, az0 = bhz, an0 = bhn;
        u64 ar1 = bhr, az1 = bhz, an1 = bhn;
#pragma unroll
        for (int i = 0; i < 16; i++) {
            ar0 = ffma2(wr[i], h0[i], ar0);
            ar1 = ffma2(wr[i], h1[i], ar1);
            az0 = ffma2(wz[i], h0[i], az0);
            az1 = ffma2(wz[i], h1[i], az1);
            an0 = ffma2(wn[i], h0[i], an0);
            an1 = ffma2(wn[i], h1[i], an1);
        }

        float lo, hi;
        unpack2(ar0, lo, hi); float hr0 = lo + hi;
        unpack2(az0, lo, hi); float hz0 = lo + hi;
        unpack2(an0, lo, hi); float hn0 = lo + hi;
        unpack2(ar1, lo, hi); float hr1 = lo + hi;
        unpack2(az1, lo, hi); float hz1 = lo + hi;
        unpack2(an1, lo, hi); float hn1 = lo + hi;

        // ---- gates, batch A ----
        float r0 = sigm(fmaf(xa, wir, bir) + hr0);
        float z0 = sigm(fmaf(xa, wiz, biz) + hz0);
        float n0 = tanh_fast(fmaf(r0, hn0, fmaf(xa, win, bin_)));
        hs0 = fmaf(z0, hs0 - n0, n0);           // (1-z)*n + z*h

        // ---- gates, batch B ----
        float r1 = sigm(fmaf(xb, wir, bir) + hr1);
        float z1 = sigm(fmaf(xb, wiz, biz) + hz1);
        float n1 = tanh_fast(fmaf(r1, hn1, fmaf(xb, win, bin_)));
        hs1 = fmaf(z1, hs1 - n1, n1);

        // ---- exchange new hidden across lanes via smem (broadcast LDS.128) ----
        sbuf[0][lane] = hs0;
        sbuf[1][lane] = hs1;
        __syncwarp();
        const ulonglong2* p0 = reinterpret_cast<const ulonglong2*>(sbuf[0]);
        const ulonglong2* p1 = reinterpret_cast<const ulonglong2*>(sbuf[1]);
#pragma unroll
        for (int i = 0; i < 8; i++) {
            ulonglong2 v0 = p0[i]; h0[2 * i] = v0.x; h0[2 * i + 1] = v0.y;
            ulonglong2 v1 = p1[i]; h1[2 * i] = v1.x; h1[2 * i + 1] = v1.y;
        }
        __syncwarp();

        xa = xna; xb = xnb;
    }

    // ---- backward direction: exactly ONE step from h=0 on x[:, T-1] ----
    // gh = 0 @ W_hh_b^T + b_hh_b = b_hh_b  (W_hh_b never needed!)
    const float wibr = Wih_b[rr], wibz = Wih_b[rz], wibn = Wih_b[rn];
    const float bibr = bih_b[rr], bibz = bih_b[rz], bibn = bih_b[rn];
    const float bhbr = bhh_b[rr], bhbz = bhh_b[rz], bhbn = bhh_b[rn];
    float xl0 = xA[T - 1], xl1 = xB[T - 1];

    float rb0 = sigm(fmaf(xl0, wibr, bibr) + bhbr);
    float zb0 = sigm(fmaf(xl0, wibz, bibz) + bhbz);
    float nb0 = tanh_fast(fmaf(rb0, bhbn, fmaf(xl0, wibn, bibn)));
    float hb0 = (1.0f - zb0) * nb0;

    float rb1 = sigm(fmaf(xl1, wibr, bibr) + bhbr);
    float zb1 = sigm(fmaf(xl1, wibz, bibz) + bhbz);
    float nb1 = tanh_fast(fmaf(rb1, bhbn, fmaf(xl1, wibn, bibn)));
    float hb1 = (1.0f - zb1) * nb1;

    // ---- MLP head: relu(concat @ W1^T + b1) @ W2^T + b2 -> sigmoid ----
    sbuf[0][lane] = hs0; sbuf[0][32 + lane] = hb0;
    sbuf[1][lane] = hs1; sbuf[1][32 + lane] = hb1;
    __syncwarp();

    if (lane < 16) {
        const float4* w4 = reinterpret_cast<const float4*>(W1 + lane * 64);
        float a0 = b1v[lane], a1 = b1v[lane];
        const float* s0 = sbuf[0];
        const float* s1 = sbuf[1];
#pragma unroll
        for (int i = 0; i < 16; i++) {
            float4 w = w4[i];
            a0 = fmaf(w.x, s0[4 * i], a0); a0 = fmaf(w.y, s0[4 * i + 1], a0);
            a0 = fmaf(w.z, s0[4 * i + 2], a0); a0 = fmaf(w.w, s0[4 * i + 3], a0);
            a1 = fmaf(w.x, s1[4 * i], a1); a1 = fmaf(w.y, s1[4 * i + 1], a1);
            a1 = fmaf(w.z, s1[4 * i + 2], a1); a1 = fmaf(w.w, s1[4 * i + 3], a1);
        }
        sbuf[0][64 + lane] = fmaxf(a0, 0.0f);
        sbuf[1][64 + lane] = fmaxf(a1, 0.0f);
    }
    __syncwarp();

    float v0 = (lane < 16) ? W2[lane] * sbuf[0][64 + lane] : 0.0f;
    float v1 = (lane < 16) ? W2[lane] * sbuf[1][64 + lane] : 0.0f;
#pragma unroll
    for (int o = 16; o > 0; o >>= 1) {
        v0 += __shfl_xor_sync(FULLMASK, v0, o);
        v1 += __shfl_xor_sync(FULLMASK, v1, o);
    }
    if (lane == 0) {
        float bb2 = b2v[0];
        out[bA] = sigm(v0 + bb2);
        if (has2) out[bB] = sigm(v1 + bb2);
    }
}

extern "C" void kernel_launch(void* const* d_in, const int* in_sizes, int n_in,
                              void* d_out, int out_size) {
    // metadata order:
    // 0:x 1:W_ih_f 2:W_hh_f 3:b_ih_f 4:b_hh_f 5:W_ih_b 6:W_hh_b 7:b_ih_b 8:b_hh_b
    // 9:W1 10:b1 11:W2 12:b2
    const float* x     = (const float*)d_in[0];
    const float* Wih_f = (const float*)d_in[1];
    const float* Whh_f = (const float*)d_in[2];
    const float* bih_f = (const float*)d_in[3];
    const float* bhh_f = (const float*)d_in[4];
    const float* Wih_b = (const float*)d_in[5];
    // d_in[6] = W_hh_b: mathematically unused (backward scan output at T-1 uses h=0)
    const float* bih_b = (const float*)d_in[7];
    const float* bhh_b = (const float*)d_in[8];
    const float* W1    = (const float*)d_in[9];
    const float* b1v   = (const float*)d_in[10];
    const float* W2    = (const float*)d_in[11];
    const float* b2v   = (const float*)d_in[12];

    int B = out_size;                 // [B,1] fp32 output
    int T = in_sizes[0] / B;          // x is [B,T,1]

    int grid = (B + 1) / 2;           // 2 batch rows per 1-warp block
    gru_bidir_kernel<<<grid, 32>>>(x, Wih_f, Whh_f, bih_f, bhh_f,
                                   Wih_b, bih_b, bhh_b,
                                   W1, b1v, W2, b2v,
                                   (float*)d_out, B, T);
}